// round 1
// baseline (speedup 1.0000x reference)
#include <cuda_runtime.h>
#include <cuda_bf16.h>

// velocity = MLP(concat(zone_embedding, person_attrs, time_vec)) — the GCN
// layers in the reference are dead code w.r.t. the returned output, and the
// person/time contributions to layer 1 are row-constant and folded into c1.

#define HID 32
#define H1  64

__device__ float g_c1[H1];   // folded layer-1 constant: bd1 + pa@Wd1[32:40] + tv@Wd1[40:56]

// ---------------------------------------------------------------------------
// Setup: compute time_vec and the folded layer-1 constant. 1 block, 64 threads.
// ---------------------------------------------------------------------------
__global__ void setup_kernel(const float* __restrict__ t,
                             const float* __restrict__ pa,
                             const float* __restrict__ Wt1, const float* __restrict__ bt1,
                             const float* __restrict__ Wt2, const float* __restrict__ bt2,
                             const float* __restrict__ Wd1, const float* __restrict__ bd1)
{
    __shared__ float u[16];
    __shared__ float tv[16];
    const int j = threadIdx.x;

    if (j < 16) u[j] = fmaxf(fmaf(t[0], Wt1[j], bt1[j]), 0.0f);
    __syncthreads();

    if (j < 16) {
        float a = bt2[j];
        #pragma unroll
        for (int i = 0; i < 16; i++) a = fmaf(u[i], Wt2[i * 16 + j], a);
        tv[j] = a;
    }
    __syncthreads();

    if (j < H1) {
        float a = bd1[j];
        #pragma unroll
        for (int p = 0; p < 8; p++)  a = fmaf(pa[p], Wd1[(HID + p) * H1 + j], a);
        #pragma unroll
        for (int i = 0; i < 16; i++) a = fmaf(tv[i], Wd1[(HID + 8 + i) * H1 + j], a);
        g_c1[j] = a;
    }
}

// ---------------------------------------------------------------------------
// Main: one thread per zone row. Weights staged transposed in smem so each
// output's weights are contiguous (float4 LDS, warp-broadcast = conflict-free).
// ---------------------------------------------------------------------------
__global__ __launch_bounds__(256)
void mlp_kernel(const float* __restrict__ emb,
                const float* __restrict__ Wd1,                        // [56,64], zone part = rows 0..31
                const float* __restrict__ Wd2, const float* __restrict__ bd2,  // [64,32],[32]
                const float* __restrict__ Wd3, const float* __restrict__ bd3,  // [32,32],[32]
                float* __restrict__ out, int nrows)
{
    __shared__ float sW1[H1 * HID];     // [j][k]: sW1[j*32+k] = Wd1[k*64+j], k<32
    __shared__ float sW2[HID * H1];     // [j][k]: sW2[j*64+k] = Wd2[k*32+j]
    __shared__ float sW3[HID * HID];    // [j][k]: sW3[j*32+k] = Wd3[k*32+j]
    __shared__ float sC1[H1], sB2[HID], sB3[HID];

    const int tid = threadIdx.x;

    for (int i = tid; i < H1 * HID; i += 256) {       // Wd1 zone part: i = k*64+j
        int k = i >> 6, j = i & 63;
        sW1[j * HID + k] = Wd1[i];
    }
    for (int i = tid; i < HID * H1; i += 256) {       // Wd2: i = k*32+j
        int k = i >> 5, j = i & 31;
        sW2[j * H1 + k] = Wd2[i];
    }
    for (int i = tid; i < HID * HID; i += 256) {      // Wd3: i = k*32+j
        int k = i >> 5, j = i & 31;
        sW3[j * HID + k] = Wd3[i];
    }
    if (tid < H1)  sC1[tid] = g_c1[tid];
    if (tid < HID) { sB2[tid] = bd2[tid]; sB3[tid] = bd3[tid]; }
    __syncthreads();

    const int row = blockIdx.x * 256 + tid;
    if (row >= nrows) return;

    // Load the 32-float embedding row (coalesced across the 8 float4 loads).
    float z[HID];
    const float4* zp = reinterpret_cast<const float4*>(emb + (size_t)row * HID);
    #pragma unroll
    for (int q = 0; q < 8; q++) {
        float4 v = zp[q];
        z[4*q+0] = v.x; z[4*q+1] = v.y; z[4*q+2] = v.z; z[4*q+3] = v.w;
    }

    // Layer 1: 32 -> 64, relu, folded constant as bias.
    float h1[H1];
    #pragma unroll
    for (int j = 0; j < H1; j++) {
        float a = sC1[j];
        const float4* w = reinterpret_cast<const float4*>(sW1 + j * HID);
        #pragma unroll
        for (int q = 0; q < 8; q++) {
            float4 ww = w[q];
            a = fmaf(z[4*q+0], ww.x, a);
            a = fmaf(z[4*q+1], ww.y, a);
            a = fmaf(z[4*q+2], ww.z, a);
            a = fmaf(z[4*q+3], ww.w, a);
        }
        h1[j] = fmaxf(a, 0.0f);
    }

    // Layer 2: 64 -> 32, relu.
    float h2[HID];
    #pragma unroll
    for (int j = 0; j < HID; j++) {
        float a = sB2[j];
        const float4* w = reinterpret_cast<const float4*>(sW2 + j * H1);
        #pragma unroll
        for (int q = 0; q < 16; q++) {
            float4 ww = w[q];
            a = fmaf(h1[4*q+0], ww.x, a);
            a = fmaf(h1[4*q+1], ww.y, a);
            a = fmaf(h1[4*q+2], ww.z, a);
            a = fmaf(h1[4*q+3], ww.w, a);
        }
        h2[j] = fmaxf(a, 0.0f);
    }

    // Layer 3: 32 -> 32, linear; vectorized store.
    float4* op = reinterpret_cast<float4*>(out + (size_t)row * HID);
    #pragma unroll
    for (int jq = 0; jq < 8; jq++) {
        float4 o;
        float* oe = &o.x;
        #pragma unroll
        for (int s = 0; s < 4; s++) {
            int j = jq * 4 + s;
            float a = sB3[j];
            const float4* w = reinterpret_cast<const float4*>(sW3 + j * HID);
            #pragma unroll
            for (int q = 0; q < 8; q++) {
                float4 ww = w[q];
                a = fmaf(h2[4*q+0], ww.x, a);
                a = fmaf(h2[4*q+1], ww.y, a);
                a = fmaf(h2[4*q+2], ww.z, a);
                a = fmaf(h2[4*q+3], ww.w, a);
            }
            oe[s] = a;
        }
        op[jq] = o;
    }
}

extern "C" void kernel_launch(void* const* d_in, const int* in_sizes, int n_in,
                              void* d_out, int out_size)
{
    // metadata order:
    // 0 t, 1 zone_embedding, 2 zone_features, 3 person_attrs, 4 edge_index(i64),
    // 5 W1, 6 b1, 7 W2, 8 b2, 9 Wt1, 10 bt1, 11 Wt2, 12 bt2,
    // 13 Wd1, 14 bd1, 15 Wd2, 16 bd2, 17 Wd3, 18 bd3
    const float* t   = (const float*)d_in[0];
    const float* emb = (const float*)d_in[1];
    const float* pa  = (const float*)d_in[3];
    const float* Wt1 = (const float*)d_in[9];
    const float* bt1 = (const float*)d_in[10];
    const float* Wt2 = (const float*)d_in[11];
    const float* bt2 = (const float*)d_in[12];
    const float* Wd1 = (const float*)d_in[13];
    const float* bd1 = (const float*)d_in[14];
    const float* Wd2 = (const float*)d_in[15];
    const float* bd2 = (const float*)d_in[16];
    const float* Wd3 = (const float*)d_in[17];
    const float* bd3 = (const float*)d_in[18];
    float* out = (float*)d_out;

    const int nrows = in_sizes[1] / HID;

    setup_kernel<<<1, 64>>>(t, pa, Wt1, bt1, Wt2, bt2, Wd1, bd1);
    mlp_kernel<<<(nrows + 255) / 256, 256>>>(emb, Wd1, Wd2, bd2, Wd3, bd3, out, nrows);
}

// round 2
// speedup vs baseline: 1.1407x; 1.1407x over previous
#include <cuda_runtime.h>
#include <cuda_bf16.h>

// velocity = MLP(concat(zone_embedding, person_attrs, time_vec)).
// GCN layers are dead code w.r.t. the output; person/time layer-1
// contributions are row-constant, folded into g_c1 by setup_kernel.
//
// R2: fma.rn.f32x2 packed math (channel pairs j,j+1 — contiguous in the
// native row-major weights, so no transpose), fused layer1->layer2 chunking
// to cut live registers, 128-thread blocks with launch_bounds(128,4).

#define HID 32
#define H1  64

typedef unsigned long long u64;

__device__ float g_c1[H1];

__device__ __forceinline__ u64 fma2(u64 a, u64 b, u64 c) {
    u64 d;
    asm("fma.rn.f32x2 %0, %1, %2, %3;" : "=l"(d) : "l"(a), "l"(b), "l"(c));
    return d;
}
__device__ __forceinline__ u64 dup2(float x) {
    u64 d;
    asm("mov.b64 %0, {%1, %1};" : "=l"(d) : "f"(x));
    return d;
}
__device__ __forceinline__ float2 unpk2(u64 v) {
    float2 r;
    asm("mov.b64 {%0, %1}, %2;" : "=f"(r.x), "=f"(r.y) : "l"(v));
    return r;
}

// ---------------------------------------------------------------------------
__global__ void setup_kernel(const float* __restrict__ t,
                             const float* __restrict__ pa,
                             const float* __restrict__ Wt1, const float* __restrict__ bt1,
                             const float* __restrict__ Wt2, const float* __restrict__ bt2,
                             const float* __restrict__ Wd1, const float* __restrict__ bd1)
{
    __shared__ float u[16];
    __shared__ float tv[16];
    const int j = threadIdx.x;

    if (j < 16) u[j] = fmaxf(fmaf(t[0], Wt1[j], bt1[j]), 0.0f);
    __syncthreads();

    if (j < 16) {
        float a = bt2[j];
        #pragma unroll
        for (int i = 0; i < 16; i++) a = fmaf(u[i], Wt2[i * 16 + j], a);
        tv[j] = a;
    }
    __syncthreads();

    if (j < H1) {
        float a = bd1[j];
        #pragma unroll
        for (int p = 0; p < 8; p++)  a = fmaf(pa[p], Wd1[(HID + p) * H1 + j], a);
        #pragma unroll
        for (int i = 0; i < 16; i++) a = fmaf(tv[i], Wd1[(HID + 8 + i) * H1 + j], a);
        g_c1[j] = a;
    }
}

// ---------------------------------------------------------------------------
// One thread per row. All weights in smem as 64-bit (f32x2) pairs in their
// native j-contiguous layout.
//   sW1u: [k=0..31][j2=0..31]   (Wd1 zone part, 64 outs)
//   sW2u: [k=0..63][j2=0..15]   (Wd2)
//   sW3u: [k=0..31][j2=0..15]   (Wd3)
// ---------------------------------------------------------------------------
__global__ __launch_bounds__(128, 4)
void mlp_kernel(const float* __restrict__ emb,
                const float* __restrict__ Wd1,
                const float* __restrict__ Wd2, const float* __restrict__ bd2,
                const float* __restrict__ Wd3, const float* __restrict__ bd3,
                float* __restrict__ out, int nrows)
{
    __shared__ u64 sW1u[32 * 32];
    __shared__ u64 sW2u[64 * 16];
    __shared__ u64 sW3u[32 * 16];
    __shared__ u64 sC1u[32], sB2u[16], sB3u[16];

    const int tid = threadIdx.x;

    {
        const u64* w1 = reinterpret_cast<const u64*>(Wd1);   // zone rows = first 1024 u64
        const u64* w2 = reinterpret_cast<const u64*>(Wd2);
        const u64* w3 = reinterpret_cast<const u64*>(Wd3);
        for (int i = tid; i < 1024; i += 128) sW1u[i] = w1[i];
        for (int i = tid; i < 1024; i += 128) sW2u[i] = w2[i];
        for (int i = tid; i <  512; i += 128) sW3u[i] = w3[i];
        const u64* c1 = reinterpret_cast<const u64*>(g_c1);
        const u64* b2 = reinterpret_cast<const u64*>(bd2);
        const u64* b3 = reinterpret_cast<const u64*>(bd3);
        if (tid < 32) sC1u[tid] = c1[tid];
        if (tid < 16) { sB2u[tid] = b2[tid]; sB3u[tid] = b3[tid]; }
    }
    __syncthreads();

    const int row = blockIdx.x * 128 + tid;
    if (row >= nrows) return;

    // Embedding row (coalesced float4 loads).
    float z[HID];
    {
        const float4* zp = reinterpret_cast<const float4*>(emb + (size_t)row * HID);
        #pragma unroll
        for (int q = 0; q < 8; q++) {
            float4 v = zp[q];
            z[4*q+0] = v.x; z[4*q+1] = v.y; z[4*q+2] = v.z; z[4*q+3] = v.w;
        }
    }

    // Layer-2 accumulators (32 floats as 16 pairs), init with bias.
    u64 acc2[16];
    #pragma unroll
    for (int q = 0; q < 16; q++) acc2[q] = sB2u[q];

    // Fused layer1 (chunked 16 outs at a time) -> relu -> layer2 accumulate.
    #pragma unroll
    for (int c = 0; c < 4; c++) {
        u64 acc1[8];
        #pragma unroll
        for (int p = 0; p < 8; p++) acc1[p] = sC1u[c * 8 + p];

        #pragma unroll
        for (int k = 0; k < 32; k++) {
            u64 zz = dup2(z[k]);
            const u64* w = sW1u + k * 32 + c * 8;
            #pragma unroll
            for (int p = 0; p < 8; p++) acc1[p] = fma2(w[p], zz, acc1[p]);
        }

        #pragma unroll
        for (int p = 0; p < 8; p++) {
            float2 h = unpk2(acc1[p]);
            const int k0 = c * 16 + 2 * p;
            u64 hh0 = dup2(fmaxf(h.x, 0.0f));
            u64 hh1 = dup2(fmaxf(h.y, 0.0f));
            const u64* w0 = sW2u + (k0 + 0) * 16;
            const u64* w1 = sW2u + (k0 + 1) * 16;
            #pragma unroll
            for (int q = 0; q < 16; q++) {
                u64 a = fma2(w0[q], hh0, acc2[q]);
                acc2[q] = fma2(w1[q], hh1, a);
            }
        }
    }

    // Layer 3: relu(acc2) -> 32 outs, linear.
    u64 acc3[16];
    #pragma unroll
    for (int q = 0; q < 16; q++) acc3[q] = sB3u[q];

    #pragma unroll
    for (int q = 0; q < 16; q++) {
        float2 h = unpk2(acc2[q]);
        const int k0 = 2 * q;
        u64 hh0 = dup2(fmaxf(h.x, 0.0f));
        u64 hh1 = dup2(fmaxf(h.y, 0.0f));
        const u64* w0 = sW3u + (k0 + 0) * 16;
        const u64* w1 = sW3u + (k0 + 1) * 16;
        #pragma unroll
        for (int p = 0; p < 16; p++) {
            u64 a = fma2(w0[p], hh0, acc3[p]);
            acc3[p] = fma2(w1[p], hh1, a);
        }
    }

    // Store 32 floats = 8 x 128-bit.
    ulonglong2* op = reinterpret_cast<ulonglong2*>(out + (size_t)row * HID);
    #pragma unroll
    for (int p = 0; p < 8; p++) {
        ulonglong2 v;
        v.x = acc3[2 * p];
        v.y = acc3[2 * p + 1];
        op[p] = v;
    }
}

extern "C" void kernel_launch(void* const* d_in, const int* in_sizes, int n_in,
                              void* d_out, int out_size)
{
    const float* t   = (const float*)d_in[0];
    const float* emb = (const float*)d_in[1];
    const float* pa  = (const float*)d_in[3];
    const float* Wt1 = (const float*)d_in[9];
    const float* bt1 = (const float*)d_in[10];
    const float* Wt2 = (const float*)d_in[11];
    const float* bt2 = (const float*)d_in[12];
    const float* Wd1 = (const float*)d_in[13];
    const float* bd1 = (const float*)d_in[14];
    const float* Wd2 = (const float*)d_in[15];
    const float* bd2 = (const float*)d_in[16];
    const float* Wd3 = (const float*)d_in[17];
    const float* bd3 = (const float*)d_in[18];
    float* out = (float*)d_out;

    const int nrows = in_sizes[1] / HID;

    setup_kernel<<<1, 64>>>(t, pa, Wt1, bt1, Wt2, bt2, Wd1, bd1);
    mlp_kernel<<<(nrows + 127) / 128, 128>>>(emb, Wd1, Wd2, bd2, Wd3, bd3, out, nrows);
}